// round 2
// baseline (speedup 1.0000x reference)
#include <cuda_runtime.h>

// ---------------- problem constants (fixed by the dataset) ----------------
#define NMAX 50000
#define EMAX 600000
#define DD   128
#define GMAX 128

// ---------------- scratch (device globals; no allocation allowed) ---------
__device__ __align__(16) float g_h[NMAX * DD];
__device__ __align__(16) float g_agg[NMAX * DD];
__device__ int g_cnt[NMAX];
__device__ int g_rowptr[NMAX + 1];
__device__ int g_cursor[NMAX];
__device__ int g_srcs[EMAX];
__device__ int g_blksum[128];
__device__ int g_gcnt[GMAX];

// ---------------- packed fp32x2 helpers (sm_103a) --------------------------
__device__ __forceinline__ unsigned long long pk2(float x, float y) {
    unsigned long long r;
    asm("mov.b64 %0, {%1,%2};" : "=l"(r) : "f"(x), "f"(y));
    return r;
}
__device__ __forceinline__ void fma2(unsigned long long& d,
                                     unsigned long long a,
                                     unsigned long long b) {
    asm("fma.rn.f32x2 %0, %1, %2, %0;" : "+l"(d) : "l"(a), "l"(b));
}
__device__ __forceinline__ float2 upk2(unsigned long long v) {
    float2 f;
    asm("mov.b64 {%0,%1}, %2;" : "=f"(f.x), "=f"(f.y) : "l"(v));
    return f;
}

// ---------------- kernels --------------------------------------------------

// zero cnt, gcnt, pooled output region
__global__ void k_zero(int N, int G, float* pooled) {
    int i = blockIdx.x * blockDim.x + threadIdx.x;
    if (i < N) g_cnt[i] = 0;
    if (i < G) g_gcnt[i] = 0;
    if (i < G * DD) pooled[i] = 0.0f;
}

__global__ void k_count(const int* __restrict__ dst, int E) {
    int e = blockIdx.x * blockDim.x + threadIdx.x;
    if (e < E) atomicAdd(&g_cnt[dst[e]], 1);
}

__global__ void k_scan1(int N) {
    __shared__ int s[512];
    int t = threadIdx.x;
    int i = blockIdx.x * 512 + t;
    int v = (i < N) ? g_cnt[i] : 0;
    s[t] = v;
    __syncthreads();
    for (int off = 1; off < 512; off <<= 1) {
        int x = (t >= off) ? s[t - off] : 0;
        __syncthreads();
        s[t] += x;
        __syncthreads();
    }
    if (i < N) g_rowptr[i] = s[t] - v;          // block-local exclusive
    if (t == 511) g_blksum[blockIdx.x] = s[511]; // block total
}

__global__ void k_scan2(int NB, int N) {
    int run = 0;
    for (int b = 0; b < NB; b++) {
        int x = g_blksum[b];
        g_blksum[b] = run;
        run += x;
    }
    g_rowptr[N] = run;  // == E
}

__global__ void k_scan3(int N) {
    int i = blockIdx.x * blockDim.x + threadIdx.x;
    if (i < N) {
        int v = g_rowptr[i] + g_blksum[i >> 9];
        g_rowptr[i] = v;
        g_cursor[i] = v;
    }
}

__global__ void k_fill(const int* __restrict__ src, const int* __restrict__ dst, int E) {
    int e = blockIdx.x * blockDim.x + threadIdx.x;
    if (e < E) {
        int d = dst[e];
        int pos = atomicAdd(&g_cursor[d], 1);
        g_srcs[pos] = src[e];
    }
}

// h = value_W[fid%128] + value_b + rwse@rwse_W + rwse_b + deg_emb[clamp(deg)]
__global__ void k_init_h(const int* __restrict__ feat_id,
                         const int* __restrict__ indeg,
                         const float* __restrict__ rwse,
                         const float* __restrict__ value_W,
                         const float* __restrict__ value_b,
                         const float* __restrict__ rwse_W,
                         const float* __restrict__ rwse_b,
                         const float* __restrict__ deg_emb,
                         int N, int RWSE, int DEGM1) {
    __shared__ float sRW[16 * DD];
    __shared__ float sVB[DD];
    __shared__ float sRB[DD];
    int tid = threadIdx.x;
    for (int i = tid; i < RWSE * DD; i += blockDim.x) sRW[i] = rwse_W[i];
    if (tid < DD) { sVB[tid] = value_b[tid]; sRB[tid] = rwse_b[tid]; }
    __syncthreads();

    int n = blockIdx.x * 8 + (tid >> 5);
    if (n >= N) return;
    int lane = tid & 31;
    int c = lane * 4;

    int fid = feat_id[n] % 128;
    int dg = indeg[n];
    dg = dg < 0 ? 0 : (dg > DEGM1 ? DEGM1 : dg);

    float4 acc = *(const float4*)(value_W + fid * DD + c);
    float4 de  = *(const float4*)(deg_emb + dg * DD + c);
    acc.x += sVB[c]     + sRB[c]     + de.x;
    acc.y += sVB[c + 1] + sRB[c + 1] + de.y;
    acc.z += sVB[c + 2] + sRB[c + 2] + de.z;
    acc.w += sVB[c + 3] + sRB[c + 3] + de.w;

    const float* rrow = rwse + (long)n * RWSE;
#pragma unroll
    for (int k = 0; k < 16; k++) {
        float r = rrow[k];
        const float* w = sRW + k * DD + c;
        acc.x = fmaf(r, w[0], acc.x);
        acc.y = fmaf(r, w[1], acc.y);
        acc.z = fmaf(r, w[2], acc.z);
        acc.w = fmaf(r, w[3], acc.w);
    }
    *(float4*)(g_h + (long)n * DD + c) = acc;
}

// agg[n] = h[n] + sum_{e in CSR(n)} h[src[e]]
__global__ void k_agg(int N) {
    int n = blockIdx.x * 8 + (threadIdx.x >> 5);
    if (n >= N) return;
    int lane = threadIdx.x & 31;
    const float4* hp = (const float4*)g_h;
    float4 acc = hp[(long)n * 32 + lane];
    int beg = g_rowptr[n], end = g_rowptr[n + 1];
    int e = beg;
    for (; e + 1 < end; e += 2) {
        int s0 = g_srcs[e], s1 = g_srcs[e + 1];
        float4 v0 = hp[(long)s0 * 32 + lane];
        float4 v1 = hp[(long)s1 * 32 + lane];
        acc.x += v0.x + v1.x;
        acc.y += v0.y + v1.y;
        acc.z += v0.z + v1.z;
        acc.w += v0.w + v1.w;
    }
    if (e < end) {
        int s0 = g_srcs[e];
        float4 v0 = hp[(long)s0 * 32 + lane];
        acc.x += v0.x; acc.y += v0.y; acc.z += v0.z; acc.w += v0.w;
    }
    ((float4*)g_agg)[(long)n * 32 + lane] = acc;
}

// fused MLP: out = relu( (relu(in@W1+b1) @ W2) * sc + sh ), BN folded into sc/sh
// smem layout (floats): W1[16384] W2[16384] B1[128] SC[128] SH[128] ROW[16*256]
#define SM_W1 0
#define SM_W2 16384
#define SM_B1 32768
#define SM_SC 32896
#define SM_SH 33024
#define SM_ROW 33152
#define SM_FLOATS (SM_ROW + 16 * 256)
#define SMEM_MLP (SM_FLOATS * 4)

__global__ void __launch_bounds__(512, 1)
k_mlp(const float* __restrict__ in, float* __restrict__ out,
      const float* __restrict__ W1, const float* __restrict__ b1,
      const float* __restrict__ W2, const float* __restrict__ b2,
      const float* __restrict__ gamma, const float* __restrict__ beta,
      const float* __restrict__ mean, const float* __restrict__ var,
      int N) {
    extern __shared__ float sm[];
    int tid = threadIdx.x;

    // load weights
    {
        const float4* w1g = (const float4*)W1;
        const float4* w2g = (const float4*)W2;
        float4* s1 = (float4*)(sm + SM_W1);
        float4* s2 = (float4*)(sm + SM_W2);
        for (int i = tid; i < 4096; i += 512) { s1[i] = w1g[i]; s2[i] = w2g[i]; }
        if (tid < DD) {
            float sc = gamma[tid] * rsqrtf(var[tid] + 1e-5f);
            sm[SM_B1 + tid] = b1[tid];
            sm[SM_SC + tid] = sc;
            sm[SM_SH + tid] = (b2[tid] - mean[tid]) * sc + beta[tid];
        }
    }
    __syncthreads();

    int warp = tid >> 5;
    int lane = tid & 31;
    int c = lane * 4;
    float* r0 = sm + SM_ROW + warp * 256;
    float* r1 = r0 + 128;
    int npairs = (N + 1) >> 1;
    int wstride = gridDim.x * 16;

    for (int p = blockIdx.x * 16 + warp; p < npairs; p += wstride) {
        int n0 = p * 2;
        int n1 = n0 + 1;
        bool v1 = (n1 < N);

        *(float4*)(r0 + c) = *(const float4*)(in + (long)n0 * DD + c);
        if (v1) *(float4*)(r1 + c) = *(const float4*)(in + (long)n1 * DD + c);
        else    *(float4*)(r1 + c) = make_float4(0.f, 0.f, 0.f, 0.f);
        __syncwarp();

        // ---- stage 1: t = relu(a @ W1 + b1) ----
        unsigned long long p0a = pk2(sm[SM_B1 + c],     sm[SM_B1 + c + 1]);
        unsigned long long p0b = pk2(sm[SM_B1 + c + 2], sm[SM_B1 + c + 3]);
        unsigned long long p1a = p0a, p1b = p0b;
#pragma unroll 8
        for (int k = 0; k < 128; k++) {
            float a0 = r0[k], a1 = r1[k];
            ulonglong2 w = *(const ulonglong2*)(sm + SM_W1 + k * DD + c);
            unsigned long long aa0 = pk2(a0, a0);
            unsigned long long aa1 = pk2(a1, a1);
            fma2(p0a, aa0, w.x); fma2(p0b, aa0, w.y);
            fma2(p1a, aa1, w.x); fma2(p1b, aa1, w.y);
        }
        __syncwarp();
        {
            float2 t0 = upk2(p0a), t1 = upk2(p0b), t2 = upk2(p1a), t3 = upk2(p1b);
            r0[c] = fmaxf(t0.x, 0.f); r0[c + 1] = fmaxf(t0.y, 0.f);
            r0[c + 2] = fmaxf(t1.x, 0.f); r0[c + 3] = fmaxf(t1.y, 0.f);
            r1[c] = fmaxf(t2.x, 0.f); r1[c + 1] = fmaxf(t2.y, 0.f);
            r1[c + 2] = fmaxf(t3.x, 0.f); r1[c + 3] = fmaxf(t3.y, 0.f);
        }
        __syncwarp();

        // ---- stage 2: out = relu( (t @ W2) * sc + sh ) ----
        p0a = 0ull; p0b = 0ull; p1a = 0ull; p1b = 0ull;
#pragma unroll 8
        for (int k = 0; k < 128; k++) {
            float a0 = r0[k], a1 = r1[k];
            ulonglong2 w = *(const ulonglong2*)(sm + SM_W2 + k * DD + c);
            unsigned long long aa0 = pk2(a0, a0);
            unsigned long long aa1 = pk2(a1, a1);
            fma2(p0a, aa0, w.x); fma2(p0b, aa0, w.y);
            fma2(p1a, aa1, w.x); fma2(p1b, aa1, w.y);
        }
        {
            float sc0 = sm[SM_SC + c],     sc1 = sm[SM_SC + c + 1];
            float sc2 = sm[SM_SC + c + 2], sc3 = sm[SM_SC + c + 3];
            float sh0 = sm[SM_SH + c],     sh1 = sm[SM_SH + c + 1];
            float sh2 = sm[SM_SH + c + 2], sh3 = sm[SM_SH + c + 3];
            float2 q0 = upk2(p0a), q1 = upk2(p0b), q2 = upk2(p1a), q3 = upk2(p1b);
            float4 o0, o1;
            o0.x = fmaxf(fmaf(q0.x, sc0, sh0), 0.f);
            o0.y = fmaxf(fmaf(q0.y, sc1, sh1), 0.f);
            o0.z = fmaxf(fmaf(q1.x, sc2, sh2), 0.f);
            o0.w = fmaxf(fmaf(q1.y, sc3, sh3), 0.f);
            o1.x = fmaxf(fmaf(q2.x, sc0, sh0), 0.f);
            o1.y = fmaxf(fmaf(q2.y, sc1, sh1), 0.f);
            o1.z = fmaxf(fmaf(q3.x, sc2, sh2), 0.f);
            o1.w = fmaxf(fmaf(q3.y, sc3, sh3), 0.f);
            *(float4*)(out + (long)n0 * DD + c) = o0;
            if (v1) *(float4*)(out + (long)n1 * DD + c) = o1;
        }
        __syncwarp();  // protect r0/r1 before next iteration overwrites
    }
}

__global__ void k_gcount(const int* __restrict__ batch, int N) {
    int i = blockIdx.x * blockDim.x + threadIdx.x;
    if (i < N) atomicAdd(&g_gcnt[batch[i]], 1);
}

__global__ void k_pool(const float* __restrict__ h, const int* __restrict__ batch,
                       float* __restrict__ pooled, int N) {
    int n = blockIdx.x * 8 + (threadIdx.x >> 5);
    if (n >= N) return;
    int lane = threadIdx.x & 31;
    int c = lane * 4;
    int g = batch[n];
    float4 v = *(const float4*)(h + (long)n * DD + c);
    atomicAdd(&pooled[g * DD + c],     v.x);
    atomicAdd(&pooled[g * DD + c + 1], v.y);
    atomicAdd(&pooled[g * DD + c + 2], v.z);
    atomicAdd(&pooled[g * DD + c + 3], v.w);
}

__global__ void k_pooldiv(float* pooled, int GD) {
    int i = blockIdx.x * blockDim.x + threadIdx.x;
    if (i < GD) {
        float cnt = (float)g_gcnt[i >> 7];
        pooled[i] /= fmaxf(cnt, 1.0f);
    }
}

// ---------------- launcher --------------------------------------------------
extern "C" void kernel_launch(void* const* d_in, const int* in_sizes, int n_in,
                              void* d_out, int out_size) {
    const int*   feat_id = (const int*)d_in[0];
    const int*   edge_index = (const int*)d_in[1];
    const int*   batch = (const int*)d_in[2];
    const float* rwse = (const float*)d_in[3];
    const int*   indeg = (const int*)d_in[4];
    const float* value_W = (const float*)d_in[5];
    const float* value_b = (const float*)d_in[6];
    const float* rwse_W = (const float*)d_in[7];
    const float* rwse_b = (const float*)d_in[8];
    const float* deg_emb = (const float*)d_in[9];
    const float* W1 = (const float*)d_in[10];
    const float* b1 = (const float*)d_in[11];
    const float* W2 = (const float*)d_in[12];
    const float* b2 = (const float*)d_in[13];
    const float* gamma = (const float*)d_in[14];
    const float* beta = (const float*)d_in[15];
    const float* mean = (const float*)d_in[16];
    const float* var = (const float*)d_in[17];

    int N = in_sizes[0];
    int E = in_sizes[1] / 2;
    int RWSE = in_sizes[3] / N;
    int DEG = in_sizes[9] / DD;
    int L = in_sizes[10] / (DD * DD);

    // CRITICAL: __device__ globals must be resolved to device addresses on the
    // host side via cudaGetSymbolAddress. Referencing them directly in host
    // code yields the host shadow symbol — which GB300's ATS happily lets the
    // GPU dereference, silently reading host zeros (root cause of R1 failure).
    float* d_gh = 0;
    float* d_gagg = 0;
    cudaGetSymbolAddress((void**)&d_gh, g_h);
    cudaGetSymbolAddress((void**)&d_gagg, g_agg);

    // Output layout: either [graph_feature (G*D) | h (N*D)] concatenated, or
    // just graph_feature. Branch defensively on out_size.
    long outRows = (long)out_size / DD;
    bool both = (outRows > (long)N);
    int G = both ? (int)(outRows - N) : (int)outRows;

    float* pooled = (float*)d_out;
    float* hout = both ? (pooled + (long)G * DD) : d_gh;

    cudaFuncSetAttribute(k_mlp, cudaFuncAttributeMaxDynamicSharedMemorySize, SMEM_MLP);

    // --- build CSR (dst-indexed) ---
    int zthreads = N > G * DD ? N : G * DD;
    k_zero<<<(zthreads + 255) / 256, 256>>>(N, G, pooled);
    k_count<<<(E + 255) / 256, 256>>>(edge_index + E, E);
    int NB = (N + 511) / 512;
    k_scan1<<<NB, 512>>>(N);
    k_scan2<<<1, 1>>>(NB, N);
    k_scan3<<<(N + 255) / 256, 256>>>(N);
    k_fill<<<(E + 255) / 256, 256>>>(edge_index, edge_index + E, E);

    // --- embeddings ---
    k_init_h<<<(N + 7) / 8, 256>>>(feat_id, indeg, rwse, value_W, value_b,
                                   rwse_W, rwse_b, deg_emb, N, RWSE, DEG - 1);

    // --- GIN layers ---
    for (int l = 0; l < L; l++) {
        k_agg<<<(N + 7) / 8, 256>>>(N);
        float* o = (l == L - 1) ? hout : d_gh;
        k_mlp<<<152, 512, SMEM_MLP>>>(d_gagg, o,
                                      W1 + l * DD * DD, b1 + l * DD,
                                      W2 + l * DD * DD, b2 + l * DD,
                                      gamma + l * DD, beta + l * DD,
                                      mean + l * DD, var + l * DD, N);
    }

    // --- graph pooling (mean) ---
    k_gcount<<<(N + 255) / 256, 256>>>(batch, N);
    k_pool<<<(N + 7) / 8, 256>>>(hout, batch, pooled, N);
    k_pooldiv<<<(G * DD + 255) / 256, 256>>>(pooled, G * DD);
}

// round 3
// speedup vs baseline: 1.4404x; 1.4404x over previous
#include <cuda_runtime.h>

// ---------------- problem constants (fixed by the dataset) ----------------
#define NMAX 50000
#define EMAX 600000
#define DD   128
#define GMAX 128

// ---------------- scratch (device globals; no allocation allowed) ---------
__device__ __align__(16) float g_h[NMAX * DD];
__device__ __align__(16) float g_agg[NMAX * DD];
__device__ int g_cnt[NMAX];
__device__ int g_rowptr[NMAX + 1];
__device__ int g_cursor[NMAX];
__device__ int g_srcs[EMAX];
__device__ int g_blksum[128];
__device__ int g_gcnt[GMAX];

// ---------------- packed fp32x2 helpers (sm_103a) --------------------------
__device__ __forceinline__ unsigned long long pk2(float x, float y) {
    unsigned long long r;
    asm("mov.b64 %0, {%1,%2};" : "=l"(r) : "f"(x), "f"(y));
    return r;
}
__device__ __forceinline__ void fma2(unsigned long long& d,
                                     unsigned long long a,
                                     unsigned long long b) {
    asm("fma.rn.f32x2 %0, %1, %2, %0;" : "+l"(d) : "l"(a), "l"(b));
}
__device__ __forceinline__ float2 upk2(unsigned long long v) {
    float2 f;
    asm("mov.b64 {%0,%1}, %2;" : "=f"(f.x), "=f"(f.y) : "l"(v));
    return f;
}

// ---------------- kernels --------------------------------------------------

// zero cnt, gcnt, pooled output region
__global__ void k_zero(int N, int G, float* pooled) {
    int i = blockIdx.x * blockDim.x + threadIdx.x;
    if (i < N) g_cnt[i] = 0;
    if (i < G) g_gcnt[i] = 0;
    if (i < G * DD) pooled[i] = 0.0f;
}

// fused: degree count + graph-size count (blocks [0,EB)) and embedding init
// (blocks [EB, EB+NBinit)) — the two halves are independent.
__global__ void k_count_init(const int* __restrict__ edge_index,
                             const int* __restrict__ batch,
                             const int* __restrict__ feat_id,
                             const int* __restrict__ indeg,
                             const float* __restrict__ rwse,
                             const float* __restrict__ value_W,
                             const float* __restrict__ value_b,
                             const float* __restrict__ rwse_W,
                             const float* __restrict__ rwse_b,
                             const float* __restrict__ deg_emb,
                             int N, int E, int RWSE, int DEGM1, int EB) {
    if (blockIdx.x < EB) {
        int e = blockIdx.x * 256 + threadIdx.x;
        if (e < E) atomicAdd(&g_cnt[edge_index[E + e]], 1);
        if (e < N) atomicAdd(&g_gcnt[batch[e]], 1);
        return;
    }
    // ---- init h ----
    __shared__ float sRW[16 * DD];
    __shared__ float sVB[DD];
    __shared__ float sRB[DD];
    int tid = threadIdx.x;
    for (int i = tid; i < RWSE * DD; i += 256) sRW[i] = rwse_W[i];
    if (tid < DD) { sVB[tid] = value_b[tid]; sRB[tid] = rwse_b[tid]; }
    __syncthreads();

    int n = (blockIdx.x - EB) * 8 + (tid >> 5);
    if (n >= N) return;
    int lane = tid & 31;
    int c = lane * 4;

    int fid = feat_id[n] % 128;
    int dg = indeg[n];
    dg = dg < 0 ? 0 : (dg > DEGM1 ? DEGM1 : dg);

    float4 acc = *(const float4*)(value_W + fid * DD + c);
    float4 de  = *(const float4*)(deg_emb + dg * DD + c);
    acc.x += sVB[c]     + sRB[c]     + de.x;
    acc.y += sVB[c + 1] + sRB[c + 1] + de.y;
    acc.z += sVB[c + 2] + sRB[c + 2] + de.z;
    acc.w += sVB[c + 3] + sRB[c + 3] + de.w;

    const float* rrow = rwse + (long)n * RWSE;
#pragma unroll
    for (int k = 0; k < 16; k++) {
        float r = rrow[k];
        const float* w = sRW + k * DD + c;
        acc.x = fmaf(r, w[0], acc.x);
        acc.y = fmaf(r, w[1], acc.y);
        acc.z = fmaf(r, w[2], acc.z);
        acc.w = fmaf(r, w[3], acc.w);
    }
    *(float4*)(g_h + (long)n * DD + c) = acc;
}

__global__ void k_scan1(int N) {
    __shared__ int s[512];
    int t = threadIdx.x;
    int i = blockIdx.x * 512 + t;
    int v = (i < N) ? g_cnt[i] : 0;
    s[t] = v;
    __syncthreads();
    for (int off = 1; off < 512; off <<= 1) {
        int x = (t >= off) ? s[t - off] : 0;
        __syncthreads();
        s[t] += x;
        __syncthreads();
    }
    if (i < N) g_rowptr[i] = s[t] - v;           // block-local exclusive
    if (t == 511) g_blksum[blockIdx.x] = s[511]; // block total
}

// parallel scan of block sums (NB <= 128) + apply to rowptr + init cursor.
// single block, 1024 threads.
__global__ void k_scan23(int NB, int N) {
    __shared__ int s[128];
    __shared__ int sx[128];
    int t = threadIdx.x;
    int v = 0;
    if (t < 128) { v = (t < NB) ? g_blksum[t] : 0; s[t] = v; }
    __syncthreads();
    for (int off = 1; off < 128; off <<= 1) {
        int x = (t >= off && t < 128) ? s[t - off] : 0;
        __syncthreads();
        if (t < 128) s[t] += x;
        __syncthreads();
    }
    if (t < 128) sx[t] = s[t] - v;  // exclusive
    __syncthreads();
    if (t == 0) g_rowptr[N] = s[127];
    for (int i = t; i < N; i += 1024) {
        int r = g_rowptr[i] + sx[i >> 9];
        g_rowptr[i] = r;
        g_cursor[i] = r;
    }
}

__global__ void k_fill(const int* __restrict__ src, const int* __restrict__ dst, int E) {
    int e = blockIdx.x * blockDim.x + threadIdx.x;
    if (e < E) {
        int d = dst[e];
        int pos = atomicAdd(&g_cursor[d], 1);
        g_srcs[pos] = src[e];
    }
}

// agg[n] = h[n] + sum_{e in CSR(n)} h[src[e]]
__global__ void k_agg(int N) {
    int n = blockIdx.x * 8 + (threadIdx.x >> 5);
    if (n >= N) return;
    int lane = threadIdx.x & 31;
    const float4* hp = (const float4*)g_h;
    float4 acc = hp[(long)n * 32 + lane];
    int beg = g_rowptr[n], end = g_rowptr[n + 1];
    int e = beg;
    for (; e + 3 < end; e += 4) {
        int s0 = g_srcs[e], s1 = g_srcs[e + 1], s2 = g_srcs[e + 2], s3 = g_srcs[e + 3];
        float4 v0 = hp[(long)s0 * 32 + lane];
        float4 v1 = hp[(long)s1 * 32 + lane];
        float4 v2 = hp[(long)s2 * 32 + lane];
        float4 v3 = hp[(long)s3 * 32 + lane];
        acc.x += (v0.x + v1.x) + (v2.x + v3.x);
        acc.y += (v0.y + v1.y) + (v2.y + v3.y);
        acc.z += (v0.z + v1.z) + (v2.z + v3.z);
        acc.w += (v0.w + v1.w) + (v2.w + v3.w);
    }
    for (; e < end; e++) {
        int s0 = g_srcs[e];
        float4 v0 = hp[(long)s0 * 32 + lane];
        acc.x += v0.x; acc.y += v0.y; acc.z += v0.z; acc.w += v0.w;
    }
    ((float4*)g_agg)[(long)n * 32 + lane] = acc;
}

// fused MLP: out = relu( (relu(in@W1+b1) @ W2) * sc + sh ), BN folded into sc/sh
// 8 nodes per warp per pass (amortize SMEM weight reads over 8 rows).
// smem layout (floats): W1[16384] W2[16384] B1[128] SC[128] SH[128] ROW[16*1024]
#define SM_W1 0
#define SM_W2 16384
#define SM_B1 32768
#define SM_SC 32896
#define SM_SH 33024
#define SM_ROW 33152
#define SM_FLOATS (SM_ROW + 16 * 1024)
#define SMEM_MLP (SM_FLOATS * 4)

__global__ void __launch_bounds__(512, 1)
k_mlp(const float* __restrict__ in, float* __restrict__ out,
      const float* __restrict__ W1g, const float* __restrict__ b1,
      const float* __restrict__ W2g, const float* __restrict__ b2,
      const float* __restrict__ gamma, const float* __restrict__ beta,
      const float* __restrict__ mean, const float* __restrict__ var,
      const int* __restrict__ batch, float* __restrict__ pooled,
      int N, int do_pool) {
    extern __shared__ float sm[];
    int tid = threadIdx.x;

    // load weights + fold BN
    {
        const float4* w1g = (const float4*)W1g;
        const float4* w2g = (const float4*)W2g;
        float4* s1 = (float4*)(sm + SM_W1);
        float4* s2 = (float4*)(sm + SM_W2);
        for (int i = tid; i < 4096; i += 512) { s1[i] = w1g[i]; s2[i] = w2g[i]; }
        if (tid < DD) {
            float sc = gamma[tid] * rsqrtf(var[tid] + 1e-5f);
            sm[SM_B1 + tid] = b1[tid];
            sm[SM_SC + tid] = sc;
            sm[SM_SH + tid] = (b2[tid] - mean[tid]) * sc + beta[tid];
        }
    }
    __syncthreads();

    int warp = tid >> 5;
    int lane = tid & 31;
    int c = lane * 4;
    float* rw = sm + SM_ROW + warp * 1024;  // 8 rows x 128
    int ngroups = (N + 7) >> 3;
    int wstride = gridDim.x * 16;

    for (int g = blockIdx.x * 16 + warp; g < ngroups; g += wstride) {
        int n0 = g << 3;
        int nv = N - n0; if (nv > 8) nv = 8;

#pragma unroll
        for (int r = 0; r < 8; r++) {
            float4 v = (r < nv) ? *(const float4*)(in + (long)(n0 + r) * DD + c)
                                : make_float4(0.f, 0.f, 0.f, 0.f);
            *(float4*)(rw + r * DD + c) = v;
        }
        __syncwarp();

        unsigned long long accA[8], accB[8];
        // ---- stage 1: t = relu(a @ W1 + b1) ----
        {
            unsigned long long bA = pk2(sm[SM_B1 + c],     sm[SM_B1 + c + 1]);
            unsigned long long bB = pk2(sm[SM_B1 + c + 2], sm[SM_B1 + c + 3]);
#pragma unroll
            for (int r = 0; r < 8; r++) { accA[r] = bA; accB[r] = bB; }
            const float* Wp = sm + SM_W1;
#pragma unroll 2
            for (int k = 0; k < DD; k += 4) {
                ulonglong2 w0 = *(const ulonglong2*)(Wp + (k + 0) * DD + c);
                ulonglong2 w1 = *(const ulonglong2*)(Wp + (k + 1) * DD + c);
                ulonglong2 w2 = *(const ulonglong2*)(Wp + (k + 2) * DD + c);
                ulonglong2 w3 = *(const ulonglong2*)(Wp + (k + 3) * DD + c);
#pragma unroll
                for (int r = 0; r < 8; r++) {
                    float4 a = *(const float4*)(rw + r * DD + k);
                    unsigned long long p;
                    p = pk2(a.x, a.x); fma2(accA[r], p, w0.x); fma2(accB[r], p, w0.y);
                    p = pk2(a.y, a.y); fma2(accA[r], p, w1.x); fma2(accB[r], p, w1.y);
                    p = pk2(a.z, a.z); fma2(accA[r], p, w2.x); fma2(accB[r], p, w2.y);
                    p = pk2(a.w, a.w); fma2(accA[r], p, w3.x); fma2(accB[r], p, w3.y);
                }
            }
        }
        __syncwarp();
#pragma unroll
        for (int r = 0; r < 8; r++) {
            float2 t0 = upk2(accA[r]), t1 = upk2(accB[r]);
            rw[r * DD + c]     = fmaxf(t0.x, 0.f);
            rw[r * DD + c + 1] = fmaxf(t0.y, 0.f);
            rw[r * DD + c + 2] = fmaxf(t1.x, 0.f);
            rw[r * DD + c + 3] = fmaxf(t1.y, 0.f);
        }
        __syncwarp();

        // ---- stage 2: out = relu( (t @ W2) * sc + sh ) ----
        {
#pragma unroll
            for (int r = 0; r < 8; r++) { accA[r] = 0ull; accB[r] = 0ull; }
            const float* Wp = sm + SM_W2;
#pragma unroll 2
            for (int k = 0; k < DD; k += 4) {
                ulonglong2 w0 = *(const ulonglong2*)(Wp + (k + 0) * DD + c);
                ulonglong2 w1 = *(const ulonglong2*)(Wp + (k + 1) * DD + c);
                ulonglong2 w2 = *(const ulonglong2*)(Wp + (k + 2) * DD + c);
                ulonglong2 w3 = *(const ulonglong2*)(Wp + (k + 3) * DD + c);
#pragma unroll
                for (int r = 0; r < 8; r++) {
                    float4 a = *(const float4*)(rw + r * DD + k);
                    unsigned long long p;
                    p = pk2(a.x, a.x); fma2(accA[r], p, w0.x); fma2(accB[r], p, w0.y);
                    p = pk2(a.y, a.y); fma2(accA[r], p, w1.x); fma2(accB[r], p, w1.y);
                    p = pk2(a.z, a.z); fma2(accA[r], p, w2.x); fma2(accB[r], p, w2.y);
                    p = pk2(a.w, a.w); fma2(accA[r], p, w3.x); fma2(accB[r], p, w3.y);
                }
            }
        }
        {
            float sc0 = sm[SM_SC + c],     sc1 = sm[SM_SC + c + 1];
            float sc2 = sm[SM_SC + c + 2], sc3 = sm[SM_SC + c + 3];
            float sh0 = sm[SM_SH + c],     sh1 = sm[SM_SH + c + 1];
            float sh2 = sm[SM_SH + c + 2], sh3 = sm[SM_SH + c + 3];
#pragma unroll
            for (int r = 0; r < 8; r++) {
                if (r >= nv) break;
                int n = n0 + r;
                float2 q0 = upk2(accA[r]), q1 = upk2(accB[r]);
                float4 o;
                o.x = fmaxf(fmaf(q0.x, sc0, sh0), 0.f);
                o.y = fmaxf(fmaf(q0.y, sc1, sh1), 0.f);
                o.z = fmaxf(fmaf(q1.x, sc2, sh2), 0.f);
                o.w = fmaxf(fmaf(q1.y, sc3, sh3), 0.f);
                *(float4*)(out + (long)n * DD + c) = o;
                if (do_pool) {
                    int gp = batch[n];
                    float* pb = pooled + gp * DD + c;
                    atomicAdd(pb,     o.x);
                    atomicAdd(pb + 1, o.y);
                    atomicAdd(pb + 2, o.z);
                    atomicAdd(pb + 3, o.w);
                }
            }
        }
        __syncwarp();  // protect rw before next iteration overwrites
    }
}

__global__ void k_pooldiv(float* pooled, int GD) {
    int i = blockIdx.x * blockDim.x + threadIdx.x;
    if (i < GD) {
        float cnt = (float)g_gcnt[i >> 7];
        pooled[i] /= fmaxf(cnt, 1.0f);
    }
}

// ---------------- launcher --------------------------------------------------
extern "C" void kernel_launch(void* const* d_in, const int* in_sizes, int n_in,
                              void* d_out, int out_size) {
    const int*   feat_id = (const int*)d_in[0];
    const int*   edge_index = (const int*)d_in[1];
    const int*   batch = (const int*)d_in[2];
    const float* rwse = (const float*)d_in[3];
    const int*   indeg = (const int*)d_in[4];
    const float* value_W = (const float*)d_in[5];
    const float* value_b = (const float*)d_in[6];
    const float* rwse_W = (const float*)d_in[7];
    const float* rwse_b = (const float*)d_in[8];
    const float* deg_emb = (const float*)d_in[9];
    const float* W1 = (const float*)d_in[10];
    const float* b1 = (const float*)d_in[11];
    const float* W2 = (const float*)d_in[12];
    const float* b2 = (const float*)d_in[13];
    const float* gamma = (const float*)d_in[14];
    const float* beta = (const float*)d_in[15];
    const float* mean = (const float*)d_in[16];
    const float* var = (const float*)d_in[17];

    int N = in_sizes[0];
    int E = in_sizes[1] / 2;
    int RWSE = in_sizes[3] / N;
    int DEG = in_sizes[9] / DD;
    int L = in_sizes[10] / (DD * DD);

    // resolve device addresses of __device__ globals (host symbol != device ptr)
    float* d_gh = 0;
    float* d_gagg = 0;
    cudaGetSymbolAddress((void**)&d_gh, g_h);
    cudaGetSymbolAddress((void**)&d_gagg, g_agg);

    long outRows = (long)out_size / DD;
    bool both = (outRows > (long)N);
    int G = both ? (int)(outRows - N) : (int)outRows;

    float* pooled = (float*)d_out;
    float* hout = both ? (pooled + (long)G * DD) : d_gh;

    cudaFuncSetAttribute(k_mlp, cudaFuncAttributeMaxDynamicSharedMemorySize, SMEM_MLP);

    // (1) zero counters + pooled
    int zthreads = N > G * DD ? N : G * DD;
    k_zero<<<(zthreads + 255) / 256, 256>>>(N, G, pooled);

    // (2) degree histogram + graph counts + embedding init (fused)
    int EB = (E + 255) / 256;
    int NBinit = (N + 7) / 8;
    k_count_init<<<EB + NBinit, 256>>>(edge_index, batch, feat_id, indeg, rwse,
                                       value_W, value_b, rwse_W, rwse_b, deg_emb,
                                       N, E, RWSE, DEG - 1, EB);

    // (3,4) scan rowptr
    int NB = (N + 511) / 512;
    k_scan1<<<NB, 512>>>(N);
    k_scan23<<<1, 1024>>>(NB, N);

    // (5) CSR fill
    k_fill<<<(E + 255) / 256, 256>>>(edge_index, edge_index + E, E);

    // (6..) GIN layers
    for (int l = 0; l < L; l++) {
        k_agg<<<(N + 7) / 8, 256>>>(N);
        bool last = (l == L - 1);
        float* o = last ? hout : d_gh;
        k_mlp<<<152, 512, SMEM_MLP>>>(d_gagg, o,
                                      W1 + l * DD * DD, b1 + l * DD,
                                      W2 + l * DD * DD, b2 + l * DD,
                                      gamma + l * DD, beta + l * DD,
                                      mean + l * DD, var + l * DD,
                                      batch, pooled, N, last ? 1 : 0);
    }

    // final mean divide
    k_pooldiv<<<(G * DD + 255) / 256, 256>>>(pooled, G * DD);
}

// round 5
// speedup vs baseline: 1.9807x; 1.3751x over previous
#include <cuda_runtime.h>
#include <cuda_bf16.h>
#include <cstdint>

// ---------------- problem constants (fixed by the dataset) ----------------
#define NMAX 50000
#define EMAX 600000
#define DD   128
#define GMAX 128

// ---------------- scratch (device globals; no allocation allowed) ---------
__device__ __align__(16) float g_h[NMAX * DD];
__device__ __align__(16) float g_agg[NMAX * DD];
__device__ int g_cnt[NMAX];
__device__ int g_rowptr[NMAX + 1];
__device__ int g_cursor[NMAX];
__device__ int g_srcs[EMAX];
__device__ int g_blksum[128];
__device__ int g_blksum2[128];
__device__ int g_gcnt[GMAX];
// pre-transposed, bf16-split weights: [2L][n*128+k]  (B[n][k] = W[k][n])
__device__ __align__(16) __nv_bfloat16 g_wh[8 * DD * DD];
__device__ __align__(16) __nv_bfloat16 g_wl[8 * DD * DD];

__device__ __forceinline__ uint32_t pkbf(__nv_bfloat16 a, __nv_bfloat16 b) {
    return ((uint32_t)__bfloat16_as_ushort(b) << 16) | (uint32_t)__bfloat16_as_ushort(a);
}

// portable tensor-core mma (PTX ISA, sm_80+; works on bare sm_103 target)
__device__ __forceinline__ void mma16816(float* c, const uint32_t* a, const uint32_t* b) {
    asm volatile(
        "mma.sync.aligned.m16n8k16.row.col.f32.bf16.bf16.f32 "
        "{%0,%1,%2,%3}, {%4,%5,%6,%7}, {%8,%9}, {%0,%1,%2,%3};"
        : "+f"(c[0]), "+f"(c[1]), "+f"(c[2]), "+f"(c[3])
        : "r"(a[0]), "r"(a[1]), "r"(a[2]), "r"(a[3]), "r"(b[0]), "r"(b[1]));
}

// ---------------- small kernels --------------------------------------------

__global__ void k_zero(int N, int G, float* pooled) {
    int i = blockIdx.x * blockDim.x + threadIdx.x;
    if (i < N) g_cnt[i] = 0;
    if (i < G) g_gcnt[i] = 0;
    if (i < G * DD) pooled[i] = 0.0f;
}

// fused: degree count + graph-size count (blocks [0,EB)) and embedding init
__global__ void k_count_init(const int* __restrict__ edge_index,
                             const int* __restrict__ batch,
                             const int* __restrict__ feat_id,
                             const int* __restrict__ indeg,
                             const float* __restrict__ rwse,
                             const float* __restrict__ value_W,
                             const float* __restrict__ value_b,
                             const float* __restrict__ rwse_W,
                             const float* __restrict__ rwse_b,
                             const float* __restrict__ deg_emb,
                             int N, int E, int RWSE, int DEGM1, int EB) {
    if (blockIdx.x < EB) {
        int e = blockIdx.x * 256 + threadIdx.x;
        if (e < E) atomicAdd(&g_cnt[edge_index[E + e]], 1);
        if (e < N) atomicAdd(&g_gcnt[batch[e]], 1);
        return;
    }
    __shared__ float sRW[16 * DD];
    __shared__ float sVB[DD];
    __shared__ float sRB[DD];
    int tid = threadIdx.x;
    for (int i = tid; i < RWSE * DD; i += 256) sRW[i] = rwse_W[i];
    if (tid < DD) { sVB[tid] = value_b[tid]; sRB[tid] = rwse_b[tid]; }
    __syncthreads();

    int n = (blockIdx.x - EB) * 8 + (tid >> 5);
    if (n >= N) return;
    int lane = tid & 31;
    int c = lane * 4;

    int fid = feat_id[n] % 128;
    int dg = indeg[n];
    dg = dg < 0 ? 0 : (dg > DEGM1 ? DEGM1 : dg);

    float4 acc = *(const float4*)(value_W + fid * DD + c);
    float4 de  = *(const float4*)(deg_emb + dg * DD + c);
    acc.x += sVB[c]     + sRB[c]     + de.x;
    acc.y += sVB[c + 1] + sRB[c + 1] + de.y;
    acc.z += sVB[c + 2] + sRB[c + 2] + de.z;
    acc.w += sVB[c + 3] + sRB[c + 3] + de.w;

    const float* rrow = rwse + (long)n * RWSE;
#pragma unroll
    for (int k = 0; k < 16; k++) {
        float r = rrow[k];
        const float* w = sRW + k * DD + c;
        acc.x = fmaf(r, w[0], acc.x);
        acc.y = fmaf(r, w[1], acc.y);
        acc.z = fmaf(r, w[2], acc.z);
        acc.w = fmaf(r, w[3], acc.w);
    }
    *(float4*)(g_h + (long)n * DD + c) = acc;
}

__global__ void k_scan1(int N) {
    __shared__ int s[512];
    int t = threadIdx.x;
    int i = blockIdx.x * 512 + t;
    int v = (i < N) ? g_cnt[i] : 0;
    s[t] = v;
    __syncthreads();
    for (int off = 1; off < 512; off <<= 1) {
        int x = (t >= off) ? s[t - off] : 0;
        __syncthreads();
        s[t] += x;
        __syncthreads();
    }
    if (i < N) g_rowptr[i] = s[t] - v;           // block-local exclusive
    if (t == 511) g_blksum[blockIdx.x] = s[511]; // block total
}

// tiny: scan the <=128 block sums (1 block, 128 threads)
__global__ void k_scanblk(int NB, int N) {
    __shared__ int s[128];
    int t = threadIdx.x;
    int v = (t < NB) ? g_blksum[t] : 0;
    s[t] = v;
    __syncthreads();
    for (int off = 1; off < 128; off <<= 1) {
        int x = (t >= off) ? s[t - off] : 0;
        __syncthreads();
        s[t] += x;
        __syncthreads();
    }
    g_blksum2[t] = s[t] - v;  // exclusive
    if (t == 127) g_rowptr[N] = s[127];
}

// wide apply
__global__ void k_apply(int N) {
    int i = blockIdx.x * blockDim.x + threadIdx.x;
    if (i < N) {
        int r = g_rowptr[i] + g_blksum2[i >> 9];
        g_rowptr[i] = r;
        g_cursor[i] = r;
    }
}

__global__ void k_fill(const int* __restrict__ src, const int* __restrict__ dst, int E) {
    int e = blockIdx.x * blockDim.x + threadIdx.x;
    if (e < E) {
        int d = dst[e];
        int pos = atomicAdd(&g_cursor[d], 1);
        g_srcs[pos] = src[e];
    }
}

// agg[n] = h[n] + sum_{e in CSR(n)} h[src[e]]
__global__ void k_agg(int N) {
    int n = blockIdx.x * 8 + (threadIdx.x >> 5);
    if (n >= N) return;
    int lane = threadIdx.x & 31;
    const float4* hp = (const float4*)g_h;
    float4 acc = hp[(long)n * 32 + lane];
    int beg = g_rowptr[n], end = g_rowptr[n + 1];
    int e = beg;
    for (; e + 3 < end; e += 4) {
        int s0 = g_srcs[e], s1 = g_srcs[e + 1], s2 = g_srcs[e + 2], s3 = g_srcs[e + 3];
        float4 v0 = hp[(long)s0 * 32 + lane];
        float4 v1 = hp[(long)s1 * 32 + lane];
        float4 v2 = hp[(long)s2 * 32 + lane];
        float4 v3 = hp[(long)s3 * 32 + lane];
        acc.x += (v0.x + v1.x) + (v2.x + v3.x);
        acc.y += (v0.y + v1.y) + (v2.y + v3.y);
        acc.z += (v0.z + v1.z) + (v2.z + v3.z);
        acc.w += (v0.w + v1.w) + (v2.w + v3.w);
    }
    for (; e < end; e++) {
        int s0 = g_srcs[e];
        float4 v0 = hp[(long)s0 * 32 + lane];
        acc.x += v0.x; acc.y += v0.y; acc.z += v0.z; acc.w += v0.w;
    }
    ((float4*)g_agg)[(long)n * 32 + lane] = acc;
}

// transpose + bf16 hi/lo split of all weight matrices: g_w*[m][n*128+k] = W_m[k][n]
__global__ void k_wprep(const float* __restrict__ W1, const float* __restrict__ W2) {
    int m = blockIdx.x;            // 0..2L-1 ; even = W1 of layer m/2, odd = W2
    int l = m >> 1;
    const float* W = (m & 1) ? (W2 + l * DD * DD) : (W1 + l * DD * DD);
    __shared__ float t[32][33];
    int tx = threadIdx.x & 31, ty8 = threadIdx.x >> 5;  // 32 x 8
    for (int tile = 0; tile < 16; tile++) {
        int tr = tile >> 2, tc = tile & 3;  // k-block, n-block
#pragma unroll
        for (int yy = 0; yy < 4; yy++) {
            int y = yy * 8 + ty8;
            t[y][tx] = W[(tr * 32 + y) * DD + tc * 32 + tx];
        }
        __syncthreads();
#pragma unroll
        for (int yy = 0; yy < 4; yy++) {
            int y = yy * 8 + ty8;
            int n = tc * 32 + y, k = tr * 32 + tx;
            float a = t[tx][y];                 // = W[k][n]
            __nv_bfloat16 h = __float2bfloat16(a);
            __nv_bfloat16 lo = __float2bfloat16(a - __bfloat162float(h));
            g_wh[m * (DD * DD) + n * DD + k] = h;
            g_wl[m * (DD * DD) + n * DD + k] = lo;
        }
        __syncthreads();
    }
}

// ---------------- tensor-core GEMM (mma.sync bf16, 3-term split) -----------
// out[n,:] = epilogue( in[n,:] @ W ), 128-node tile per CTA iteration.
// mode 0: out = relu(D + b1)            (q1 = b1)
// mode 1: out = relu(D*sc + sh)         (q1..q5 = gamma,beta,mean,var,b2)
// mode 2: mode 1 + atomic mean-pool accumulate
#define PADK 136                       // bf16 elems per smem row (pad 8: 16B-aligned rows, conflict-free frags)
#define MATB (128 * PADK * 2)          // 34816 bytes per matrix
#define OFF_AH 1024
#define OFF_AL (OFF_AH + MATB)
#define OFF_BH (OFF_AL + MATB)
#define OFF_BL (OFF_BH + MATB)
#define SMEM_GEMM (OFF_BL + MATB)      // 140288 bytes

__global__ void __launch_bounds__(512, 1)
k_gemm(const float* __restrict__ in, float* __restrict__ out,
       int wsel, int mode,
       const float* __restrict__ q1, const float* __restrict__ q2,
       const float* __restrict__ q3, const float* __restrict__ q4,
       const float* __restrict__ q5,
       const int* __restrict__ batch, float* __restrict__ pooled,
       int N) {
    extern __shared__ char smc[];
    float* sm = (float*)smc;           // [0,128): sc  [128,256): sh
    __nv_bfloat16* sAH = (__nv_bfloat16*)(smc + OFF_AH);
    __nv_bfloat16* sAL = (__nv_bfloat16*)(smc + OFF_AL);
    __nv_bfloat16* sBH = (__nv_bfloat16*)(smc + OFF_BH);
    __nv_bfloat16* sBL = (__nv_bfloat16*)(smc + OFF_BL);
    int tid = threadIdx.x;

    // header: per-column scale/shift (BN folded)
    if (tid < 128) {
        float sc, shv;
        if (mode == 0) { sc = 1.0f; shv = q1[tid]; }
        else {
            sc = q1[tid] * rsqrtf(q4[tid] + 1e-5f);
            shv = (q5[tid] - q3[tid]) * sc + q2[tid];
        }
        sm[tid]       = sc;
        sm[128 + tid] = shv;
    }

    // B load (once): [n][k] bf16 hi/lo, 2048 uint4 per matrix
    {
        const uint4* srch = (const uint4*)(g_wh + wsel * (DD * DD));
        const uint4* srcl = (const uint4*)(g_wl + wsel * (DD * DD));
        for (int i = tid; i < 2048; i += 512) {
            int n = i >> 4, k8 = (i & 15) << 3;
            int off = n * PADK + k8;
            *(uint4*)(sBH + off) = srch[i];
            *(uint4*)(sBL + off) = srcl[i];
        }
    }

    int w = tid >> 5, lane = tid & 31;
    int wm = w & 3, wn = w >> 2;       // 4x4 warp grid, each 32x32 output
    int tg = lane >> 2;                // 0..7
    int tq = lane & 3;                 // 0..3

    int ntiles = (N + 127) >> 7;
    bool first = true;

    for (int tile = blockIdx.x; tile < ntiles; tile += gridDim.x) {
        int n0 = tile << 7;
        __syncthreads();               // protect A smem (and header/B on first pass)
        // ---- stage A tile: fp32 -> bf16 hi/lo ----
        for (int i = tid; i < 4096; i += 512) {     // 128 rows x 32 float4
            int m = i >> 5, k4 = (i & 31) << 2;
            int gn = n0 + m;
            float4 a = (gn < N) ? *(const float4*)(in + (long)gn * DD + k4)
                                : make_float4(0.f, 0.f, 0.f, 0.f);
            __nv_bfloat16 h0 = __float2bfloat16(a.x);
            __nv_bfloat16 h1 = __float2bfloat16(a.y);
            __nv_bfloat16 h2 = __float2bfloat16(a.z);
            __nv_bfloat16 h3 = __float2bfloat16(a.w);
            __nv_bfloat16 l0 = __float2bfloat16(a.x - __bfloat162float(h0));
            __nv_bfloat16 l1 = __float2bfloat16(a.y - __bfloat162float(h1));
            __nv_bfloat16 l2 = __float2bfloat16(a.z - __bfloat162float(h2));
            __nv_bfloat16 l3 = __float2bfloat16(a.w - __bfloat162float(h3));
            int off = m * PADK + k4;
            *(uint32_t*)(sAH + off)     = pkbf(h0, h1);
            *(uint32_t*)(sAH + off + 2) = pkbf(h2, h3);
            *(uint32_t*)(sAL + off)     = pkbf(l0, l1);
            *(uint32_t*)(sAL + off + 2) = pkbf(l2, l3);
        }
        __syncthreads();
        first = false;

        // ---- mainloop: 8 k-steps of 16, 3 terms ----
        float c[8][4];
#pragma unroll
        for (int i = 0; i < 8; i++) { c[i][0] = c[i][1] = c[i][2] = c[i][3] = 0.f; }

#pragma unroll
        for (int ks = 0; ks < 8; ks++) {
            int k0 = ks * 16 + tq * 2;
            uint32_t ah[2][4], al[2][4], bh[4][2], bl[4][2];
#pragma unroll
            for (int mi = 0; mi < 2; mi++) {
                int base = (wm * 32 + mi * 16 + tg) * PADK + k0;
                ah[mi][0] = *(const uint32_t*)(sAH + base);
                ah[mi][1] = *(const uint32_t*)(sAH + base + 8 * PADK);
                ah[mi][2] = *(const uint32_t*)(sAH + base + 8);
                ah[mi][3] = *(const uint32_t*)(sAH + base + 8 * PADK + 8);
                al[mi][0] = *(const uint32_t*)(sAL + base);
                al[mi][1] = *(const uint32_t*)(sAL + base + 8 * PADK);
                al[mi][2] = *(const uint32_t*)(sAL + base + 8);
                al[mi][3] = *(const uint32_t*)(sAL + base + 8 * PADK + 8);
            }
#pragma unroll
            for (int ni = 0; ni < 4; ni++) {
                int base = (wn * 32 + ni * 8 + tg) * PADK + k0;
                bh[ni][0] = *(const uint32_t*)(sBH + base);
                bh[ni][1] = *(const uint32_t*)(sBH + base + 8);
                bl[ni][0] = *(const uint32_t*)(sBL + base);
                bl[ni][1] = *(const uint32_t*)(sBL + base + 8);
            }
#pragma unroll
            for (int mi = 0; mi < 2; mi++) {
#pragma unroll
                for (int ni = 0; ni < 4; ni++) {
                    float* cc = c[mi * 4 + ni];
                    mma16816(cc, ah[mi], bh[ni]);
                    mma16816(cc, al[mi], bh[ni]);
                    mma16816(cc, ah[mi], bl[ni]);
                }
            }
        }

        // ---- epilogue: scale/shift + relu (+ pool) ----
#pragma unroll
        for (int mi = 0; mi < 2; mi++) {
#pragma unroll
            for (int ni = 0; ni < 4; ni++) {
                int colc = wn * 32 + ni * 8 + tq * 2;
                float sc0 = sm[colc], sc1 = sm[colc + 1];
                float sh0 = sm[128 + colc], sh1 = sm[128 + colc + 1];
                const float* cc = c[mi * 4 + ni];
                int r0 = n0 + wm * 32 + mi * 16 + tg;
                int r1 = r0 + 8;
                if (r0 < N) {
                    float2 o;
                    o.x = fmaxf(fmaf(cc[0], sc0, sh0), 0.f);
                    o.y = fmaxf(fmaf(cc[1], sc1, sh1), 0.f);
                    *(float2*)(out + (long)r0 * DD + colc) = o;
                    if (mode == 2) {
                        int g = batch[r0];
                        atomicAdd(pooled + g * DD + colc, o.x);
                        atomicAdd(pooled + g * DD + colc + 1, o.y);
                    }
                }
                if (r1 < N) {
                    float2 o;
                    o.x = fmaxf(fmaf(cc[2], sc0, sh0), 0.f);
                    o.y = fmaxf(fmaf(cc[3], sc1, sh1), 0.f);
                    *(float2*)(out + (long)r1 * DD + colc) = o;
                    if (mode == 2) {
                        int g = batch[r1];
                        atomicAdd(pooled + g * DD + colc, o.x);
                        atomicAdd(pooled + g * DD + colc + 1, o.y);
                    }
                }
            }
        }
    }
    (void)first;
}

__global__ void k_pooldiv(float* pooled, int GD) {
    int i = blockIdx.x * blockDim.x + threadIdx.x;
    if (i < GD) {
        float cnt = (float)g_gcnt[i >> 7];
        pooled[i] /= fmaxf(cnt, 1.0f);
    }
}

// ---------------- launcher --------------------------------------------------
extern "C" void kernel_launch(void* const* d_in, const int* in_sizes, int n_in,
                              void* d_out, int out_size) {
    const int*   feat_id = (const int*)d_in[0];
    const int*   edge_index = (const int*)d_in[1];
    const int*   batch = (const int*)d_in[2];
    const float* rwse = (const float*)d_in[3];
    const int*   indeg = (const int*)d_in[4];
    const float* value_W = (const float*)d_in[5];
    const float* value_b = (const float*)d_in[6];
    const float* rwse_W = (const float*)d_in[7];
    const float* rwse_b = (const float*)d_in[8];
    const float* deg_emb = (const float*)d_in[9];
    const float* W1 = (const float*)d_in[10];
    const float* b1 = (const float*)d_in[11];
    const float* W2 = (const float*)d_in[12];
    const float* b2 = (const float*)d_in[13];
    const float* gamma = (const float*)d_in[14];
    const float* beta = (const float*)d_in[15];
    const float* mean = (const float*)d_in[16];
    const float* var = (const float*)d_in[17];

    int N = in_sizes[0];
    int E = in_sizes[1] / 2;
    int RWSE = in_sizes[3] / N;
    int DEG = in_sizes[9] / DD;
    int L = in_sizes[10] / (DD * DD);

    // resolve device addresses of __device__ globals (host symbol != device ptr)
    float* d_gh = 0;
    float* d_gagg = 0;
    cudaGetSymbolAddress((void**)&d_gh, g_h);
    cudaGetSymbolAddress((void**)&d_gagg, g_agg);

    long outRows = (long)out_size / DD;
    bool both = (outRows > (long)N);
    int G = both ? (int)(outRows - N) : (int)outRows;

    float* pooled = (float*)d_out;
    float* hout = both ? (pooled + (long)G * DD) : d_gh;

    cudaFuncSetAttribute(k_gemm, cudaFuncAttributeMaxDynamicSharedMemorySize, SMEM_GEMM);

    // (1) zero counters + pooled
    int zthreads = N > G * DD ? N : G * DD;
    k_zero<<<(zthreads + 255) / 256, 256>>>(N, G, pooled);

    // (2) degree histogram + graph counts + embedding init (fused)
    int EB = (E + 255) / 256;
    int NBinit = (N + 7) / 8;
    k_count_init<<<EB + NBinit, 256>>>(edge_index, batch, feat_id, indeg, rwse,
                                       value_W, value_b, rwse_W, rwse_b, deg_emb,
                                       N, E, RWSE, DEG - 1, EB);

    // (3) weight transpose + bf16 split (independent of CSR build)
    k_wprep<<<2 * L, 256>>>(W1, W2);

    // (4,5,6) rowptr scan
    int NB = (N + 511) / 512;
    k_scan1<<<NB, 512>>>(N);
    k_scanblk<<<1, 128>>>(NB, N);
    k_apply<<<(N + 255) / 256, 256>>>(N);

    // (7) CSR fill
    k_fill<<<(E + 255) / 256, 256>>>(edge_index, edge_index + E, E);

    // (8..) GIN layers
    int ntiles = (N + 127) / 128;
    int ggrid = ntiles < 148 ? ntiles : 148;
    for (int l = 0; l < L; l++) {
        k_agg<<<(N + 7) / 8, 256>>>(N);
        bool last = (l == L - 1);
        // GEMM1: t = relu(agg @ W1 + b1)   (in-place on g_agg)
        k_gemm<<<ggrid, 512, SMEM_GEMM>>>(d_gagg, d_gagg, 2 * l, 0,
                                          b1 + l * DD, 0, 0, 0, 0,
                                          batch, pooled, N);
        // GEMM2: h = relu(BN(t @ W2 + b2)) (+pool on last layer)
        k_gemm<<<ggrid, 512, SMEM_GEMM>>>(d_gagg, last ? hout : d_gh,
                                          2 * l + 1, last ? 2 : 1,
                                          gamma + l * DD, beta + l * DD,
                                          mean + l * DD, var + l * DD, b2 + l * DD,
                                          batch, pooled, N);
    }

    // final mean divide
    k_pooldiv<<<(G * DD + 255) / 256, 256>>>(pooled, G * DD);
}